// round 15
// baseline (speedup 1.0000x reference)
#include <cuda_runtime.h>
#include <cuda_bf16.h>
#include <cstdint>

#define VOX (48*48*48)
typedef unsigned long long u64;
typedef unsigned int u32;

// Device globals
__device__ __nv_bfloat16 g_w1a[3 * 9 * 64 * 72];  // conv1 A: [dz][tap9][oc64][hi32|lo32|pad]
__device__ u32 g_w2frag[13824];                   // conv2 B frags (k-permuted)
__device__ char g_feats[48 * 48 * 50 * 144];      // pre-split features, sF row format

__device__ __forceinline__ void fma2(u64& acc, u64 a, u64 b) {
    asm("fma.rn.f32x2 %0, %1, %2, %0;" : "+l"(acc) : "l"(a), "l"(b));
}
__device__ __forceinline__ u64 dup2(float v) {
    u64 r; asm("mov.b64 %0, {%1, %1};" : "=l"(r) : "f"(v)); return r;
}
__device__ __forceinline__ u32 cvt2bf(float a, float b) {
    u32 r; asm("cvt.rn.bf16x2.f32 %0, %1, %2;" : "=r"(r) : "f"(b), "f"(a)); return r;
}
__device__ __forceinline__ void ldsm4(u32& r0, u32& r1, u32& r2, u32& r3, u32 a) {
    asm volatile("ldmatrix.sync.aligned.m8n8.x4.shared.b16 {%0,%1,%2,%3}, [%4];"
                 : "=r"(r0), "=r"(r1), "=r"(r2), "=r"(r3) : "r"(a));
}
__device__ __forceinline__ void mmabf(float* d, const u32* a, const u32* b) {
    asm volatile(
        "mma.sync.aligned.m16n8k16.row.col.f32.bf16.bf16.f32 "
        "{%0,%1,%2,%3}, {%4,%5,%6,%7}, {%8,%9}, {%0,%1,%2,%3};"
        : "+f"(d[0]), "+f"(d[1]), "+f"(d[2]), "+f"(d[3])
        : "r"(a[0]), "r"(a[1]), "r"(a[2]), "r"(a[3]), "r"(b[0]), "r"(b[1]));
}
__device__ __forceinline__ void cpasync16(u32 dst, const void* src) {
    asm volatile("cp.async.cg.shared.global [%0], [%1], 16;"
                 :: "r"(dst), "l"(src));
}

// ---------------------------------------------------------------------------
// Prep A: weights (unchanged)
// ---------------------------------------------------------------------------
extern "C" __global__ void k_prep(const float* __restrict__ w1,
                                  const float* __restrict__ w2)
{
    int id = blockIdx.x * 256 + threadIdx.x;
    if (id < 13824) {
        int breg  = id & 1;
        int entry = id >> 1;
        int lane  = entry & 31;
        int q     = entry >> 5;
        int pass  = q & 1;
        int kt    = (q >> 1) & 3;
        int nt    = q >> 3;
        int tr = lane >> 2, tc = lane & 3;
        int mc = nt * 8 + tr;
        int k0 = kt * 16 + 2 * tc + breg * 8;
        int ocA = ((k0 >> 4) << 4) + ((k0 >> 1) & 7) + ((k0 & 1) << 3);
        int k1 = k0 + 1;
        int ocB = ((k1 >> 4) << 4) + ((k1 >> 1) & 7) + ((k1 & 1) << 3);
        float v0 = w2[mc * 64 + ocA];
        float v1 = w2[mc * 64 + ocB];
        __nv_bfloat16 h0 = __float2bfloat16(v0);
        __nv_bfloat16 h1 = __float2bfloat16(v1);
        u32 out;
        if (pass == 0) {
            out = ((u32)__bfloat16_as_ushort(h1) << 16) | (u32)__bfloat16_as_ushort(h0);
        } else {
            __nv_bfloat16 l0 = __float2bfloat16(v0 - __bfloat162float(h0));
            __nv_bfloat16 l1 = __float2bfloat16(v1 - __bfloat162float(h1));
            out = ((u32)__bfloat16_as_ushort(l1) << 16) | (u32)__bfloat16_as_ushort(l0);
        }
        g_w2frag[id] = out;
    } else if (id < 13824 + 55296) {
        int q = id - 13824;
        int ci = q & 31;
        int r  = q >> 5;
        int oc = r & 63;
        int r2 = r >> 6;
        int tap = r2 % 9, dz = r2 / 9;
        float v = w1[oc * 864 + ci * 27 + dz * 9 + tap];
        __nv_bfloat16 hi = __float2bfloat16(v);
        __nv_bfloat16 lo = __float2bfloat16(v - __bfloat162float(hi));
        int base = ((dz * 9 + tap) * 64 + oc) * 72;
        g_w1a[base + ci]      = hi;
        g_w1a[base + 32 + ci] = lo;
    }
}

// ---------------------------------------------------------------------------
// Prep B: features -> bf16 hi/lo rows (unchanged)
// ---------------------------------------------------------------------------
extern "C" __global__ void k_prep_feat(const float* __restrict__ feat)
{
    int id = blockIdx.x * 256 + threadIdx.x;
    if (id >= 48 * 48 * 50 * 16) return;
    int ci2 = id & 15;
    int q   = id >> 4;
    int wp  = q % 50;
    int row = q;
    int y   = (q / 50) % 48;
    int z   = q / (50 * 48);
    int w = min(max(wp - 1, 0), 47);
    long gi = (long)(2 * ci2) * VOX + (z * 48 + y) * 48 + w;
    float f0 = feat[gi];
    float f1 = feat[gi + VOX];
    u32 hp = cvt2bf(f0, f1);
    float r0 = f0 - __uint_as_float(hp << 16);
    float r1 = f1 - __uint_as_float(hp & 0xffff0000u);
    u32 lp = cvt2bf(r0, r1);
    char* dst = g_feats + (size_t)row * 144;
    *(u32*)(dst + ci2 * 4)      = hp;
    *(u32*)(dst + 64 + ci2 * 4) = lp;
}

// ---------------------------------------------------------------------------
// Fused kernel, 256 threads, 2 CTAs/SM, grid (24,48). Block = (d, 2 h-rows).
// conv1 warps: mw = warp&1 (oc pair), nw = (warp>>1)&1 (h row),
//              kcw = warp>>2 (ci half). Warp tile 2m x 6n x 1kc.
// Partial D over kc combined via smem exchange before phase 2.
// smem: sF 2x28800 [0,57600) ; sA 2x27648 [57600,112896)
//       exchange: [57600, 57600+24576) ; phase2 sHu [0,26112) ;
//       phase3 sMt [26112,110592)
// ---------------------------------------------------------------------------
extern "C" __global__ void __launch_bounds__(256, 2) k_fused(
    const float* __restrict__ b1, const float* __restrict__ x,
    const float* __restrict__ b2, float* __restrict__ out)
{
    extern __shared__ char sm[];
    const u32 sFb = (u32)__cvta_generic_to_shared(sm);
    const u32 sAb = sFb + 57600;

    const int tid  = threadIdx.x;
    const int lane = tid & 31;
    const int warp = tid >> 5;
    const int mw  = warp & 1;
    const int nw  = (warp >> 1) & 1;
    const int kcw = warp >> 2;
    const int grp = lane >> 3, r8 = lane & 7;
    const int tr = lane >> 2, tc = lane & 3;
    const int h0 = blockIdx.x * 2;
    const int d  = blockIdx.y;

    auto issueA = [&](int s, int buf) {
        const char* src = (const char*)g_w1a + (size_t)s * 27648;
        u32 dst = sAb + buf * 27648;
        for (int t = tid; t < 1728; t += 256)
            cpasync16(dst + t * 16, src + t * 16);
    };
    auto issueF = [&](int dz, int buf) {
        int z = min(max(d - 1 + dz, 0), 47);
        u32 dst = sFb + buf * 28800;
#pragma unroll
        for (int hh = 0; hh < 4; hh++) {
            int y = min(max(h0 - 1 + hh, 0), 47);
            const char* src = g_feats + (size_t)((z * 48 + y) * 50) * 144;
            for (int t = tid; t < 450; t += 256)
                cpasync16(dst + hh * 7200 + t * 16, src + t * 16);
        }
    };

    // ======================= Phase 1: conv1 (single-sync pipeline) ==========
    float D[2][6][4];
#pragma unroll
    for (int i = 0; i < 2; i++)
#pragma unroll
        for (int j = 0; j < 6; j++)
#pragma unroll
            for (int c = 0; c < 4; c++) D[i][j][c] = 0.0f;

    issueF(0, 0);
    issueA(0, 0);
    asm volatile("cp.async.commit_group;" ::: "memory");

#pragma unroll 1
    for (int s = 0; s < 9; s++) {
        const int dz = s / 3, dy = s % 3;
        const int abuf = s & 1;
        const int fbuf = dz & 1;

        asm volatile("cp.async.wait_group 0;" ::: "memory");
        __syncthreads();     // stage s visible; everyone past stage s-1 compute
        if (s < 8) {
            issueA(s + 1, abuf ^ 1);
            if (dy == 2) issueF(dz + 1, fbuf ^ 1);
            asm volatile("cp.async.commit_group;" ::: "memory");
        }

        const u32 slabBase = sAb + abuf * 27648;
        const u32 fBase    = sFb + fbuf * 28800;
#pragma unroll 1
        for (int dx = 0; dx < 3; dx++) {
            const u32 tapBase = slabBase + dx * 64 * 144;
            const int rowBase = (nw + dy) * 50 + dx;
            // A: 2 m-tiles (hi + lo), kc = kcw
            u32 a_hi[2][4], a_lo[2][4];
#pragma unroll
            for (int i = 0; i < 2; i++) {
                u32 ab = tapBase
                       + ((2 * mw + i) * 16 + (grp & 1) * 8 + r8) * 144
                       + (grp >> 1) * 16 + kcw * 32;
                ldsm4(a_hi[i][0], a_hi[i][1], a_hi[i][2], a_hi[i][3], ab);
                ldsm4(a_lo[i][0], a_lo[i][1], a_lo[i][2], a_lo[i][3], ab + 64);
            }
            // B: 6 n8 tiles, hi and lo (3 x4 each), kc = kcw
            u32 bh[6][2], bl[6][2];
#pragma unroll
            for (int jj = 0; jj < 3; jj++) {
                int rowI = rowBase + jj * 16 + (grp >> 1) * 8 + r8;
                u32 bb = fBase + rowI * 144 + (grp & 1) * 16 + kcw * 32;
                ldsm4(bh[2 * jj][0], bh[2 * jj][1],
                      bh[2 * jj + 1][0], bh[2 * jj + 1][1], bb);
                ldsm4(bl[2 * jj][0], bl[2 * jj][1],
                      bl[2 * jj + 1][0], bl[2 * jj + 1][1], bb + 64);
            }
#pragma unroll
            for (int i = 0; i < 2; i++)
#pragma unroll
                for (int j = 0; j < 6; j++) {
                    mmabf(D[i][j], a_hi[i], bh[j]);
                    mmabf(D[i][j], a_lo[i], bh[j]);
                    mmabf(D[i][j], a_hi[i], bl[j]);
                }
        }
    }
    __syncthreads();   // all warps done reading sF/sA

    // ====== kc-partial exchange: kcw=1 warps dump D, kcw=0 warps reduce =====
    float* ex = (float*)(sm + 57600);   // 24576 B: [pair4][ij12][lane32][4]
    const int pair = nw * 2 + mw;
    if (kcw == 1) {
#pragma unroll
        for (int i = 0; i < 2; i++)
#pragma unroll
            for (int j = 0; j < 6; j++)
                *(float4*)&ex[(((pair * 12) + i * 6 + j) * 32 + lane) * 4] =
                    *(float4*)D[i][j];
    }
    __syncthreads();

    // ====== Phase 2: reduce + silu + bf16 hi/lo split into sHu ==============
    u32* sHu = (u32*)sm;
    const u32 sHb = sFb;
    if (kcw == 0) {
#pragma unroll
        for (int i = 0; i < 2; i++) {
            int oc0 = (2 * mw + i) * 16 + tr;
            int jcol = (2 * mw + i) * 8 + tr;
            float bias0 = b1[oc0], bias1 = b1[oc0 + 8];
#pragma unroll
            for (int j = 0; j < 6; j++) {
                float4 o = *(float4*)&ex[(((pair * 12) + i * 6 + j) * 32 + lane) * 4];
                int vl = nw * 48 + j * 8 + 2 * tc;
                float v0 = D[i][j][0] + o.x + bias0;
                float v1 = D[i][j][1] + o.y + bias0;
                float v2 = D[i][j][2] + o.z + bias1;
                float v3 = D[i][j][3] + o.w + bias1;
                v0 = v0 / (1.0f + __expf(-v0));
                v1 = v1 / (1.0f + __expf(-v1));
                v2 = v2 / (1.0f + __expf(-v2));
                v3 = v3 / (1.0f + __expf(-v3));
                u32 hp0 = cvt2bf(v0, v2);
                u32 hp1 = cvt2bf(v1, v3);
                u32 lp0 = cvt2bf(v0 - __uint_as_float(hp0 << 16),
                                 v2 - __uint_as_float(hp0 & 0xffff0000u));
                u32 lp1 = cvt2bf(v1 - __uint_as_float(hp1 << 16),
                                 v3 - __uint_as_float(hp1 & 0xffff0000u));
                sHu[vl * 68 + jcol]            = hp0;
                sHu[vl * 68 + 32 + jcol]       = lp0;
                sHu[(vl + 1) * 68 + jcol]      = hp1;
                sHu[(vl + 1) * 68 + 32 + jcol] = lp1;
            }
        }
    }
    __syncthreads();

    // ======================= Phase 3: conv2 GEMM -> softmax -> apply =======
    float* sMt = (float*)(sm + 26112);   // 96 x 220 fp32
    const uint2* w2f = (const uint2*)g_w2frag;

    {
        const int nnt = (warp < 3) ? 4 : 3;
#pragma unroll 1
        for (int mh = 0; mh < 2; mh++) {
            float Dv[4][3][4];
#pragma unroll
            for (int t = 0; t < 4; t++)
#pragma unroll
                for (int mi = 0; mi < 3; mi++)
#pragma unroll
                    for (int c = 0; c < 4; c++) Dv[t][mi][c] = 0.0f;

#pragma unroll
            for (int kt = 0; kt < 4; kt++) {
                u32 ah[3][4], al[3][4];
#pragma unroll
                for (int mi = 0; mi < 3; mi++) {
                    int mt = mh * 3 + mi;
                    u32 ab = sHb + (mt * 16 + (grp & 1) * 8 + r8) * 272
                           + (grp >> 1) * 16 + kt * 32;
                    ldsm4(ah[mi][0], ah[mi][1], ah[mi][2], ah[mi][3], ab);
                    ldsm4(al[mi][0], al[mi][1], al[mi][2], al[mi][3], ab + 128);
                }
#pragma unroll
                for (int t = 0; t < 4; t++) {
                    if (t >= nnt) break;
                    int nt = warp + 8 * t;
                    uint2 bhv = w2f[((nt * 4 + kt) * 2 + 0) * 32 + lane];
                    uint2 blv = w2f[((nt * 4 + kt) * 2 + 1) * 32 + lane];
                    u32 bh2[2] = { bhv.x, bhv.y };
                    u32 bl2[2] = { blv.x, blv.y };
#pragma unroll
                    for (int mi = 0; mi < 3; mi++) {
                        mmabf(Dv[t][mi], ah[mi], bh2);
                        mmabf(Dv[t][mi], al[mi], bh2);
                        mmabf(Dv[t][mi], ah[mi], bl2);
                    }
                }
            }
#pragma unroll
            for (int t = 0; t < 4; t++) {
                if (t >= nnt) break;
                int nt = warp + 8 * t;
                int mcA = nt * 8 + 2 * tc;
                int mcB = mcA + 1;
                float bA = b2[mcA], bB = b2[mcB];
                int iA = (mcA % 27) * 8 + mcA / 27;
                int iB = (mcB % 27) * 8 + mcB / 27;
#pragma unroll
                for (int mi = 0; mi < 3; mi++) {
                    int v0 = (mh * 3 + mi) * 16 + tr;
                    sMt[v0 * 220 + iA]       = Dv[t][mi][0] + bA;
                    sMt[v0 * 220 + iB]       = Dv[t][mi][1] + bB;
                    sMt[(v0 + 8) * 220 + iA] = Dv[t][mi][2] + bA;
                    sMt[(v0 + 8) * 220 + iB] = Dv[t][mi][3] + bB;
                }
            }
        }
    }
    __syncthreads();

    // --- softmax over n per (vl, g-pair) ---
    for (int s = tid; s < 384; s += 256) {
        int vl = s >> 2, gp = s & 3;
        float* p = &sMt[vl * 220 + 2 * gp];
        float2 m0 = *(float2*)p;
        float mx0 = m0.x, mx1 = m0.y;
#pragma unroll
        for (int n = 1; n < 27; n++) {
            float2 mv = *(float2*)(p + n * 8);
            mx0 = fmaxf(mx0, mv.x);
            mx1 = fmaxf(mx1, mv.y);
        }
        float e0[27], e1[27];
        float s0 = 0.0f, s1 = 0.0f;
#pragma unroll
        for (int n = 0; n < 27; n++) {
            float2 mv = *(float2*)(p + n * 8);
            e0[n] = __expf(mv.x - mx0); s0 += e0[n];
            e1[n] = __expf(mv.y - mx1); s1 += e1[n];
        }
        float i0 = 1.0f / s0, i1 = 1.0f / s1;
#pragma unroll
        for (int n = 0; n < 27; n++)
            *(float2*)(p + n * 8) = make_float2(e0[n] * i0, e1[n] * i1);
    }
    __syncthreads();

    // --- apply ---
    int zd[3];
#pragma unroll
    for (int t = 0; t < 3; t++) zd[t] = min(max(d + t - 1, 0), 47);

#pragma unroll 1
    for (int p = tid; p < 768; p += 256) {
        int vl = p % 96, cq = p / 96;
        int hr = (vl >= 48);
        int v  = vl - (hr ? 48 : 0);
        int hB = h0 + hr;
        int zh[3], zw[3];
#pragma unroll
        for (int t = 0; t < 3; t++) zh[t] = min(max(hB + t - 1, 0), 47);
        zw[0] = max(v - 1, 0); zw[1] = v; zw[2] = min(v + 1, 47);
        const float* mB = &sMt[vl * 220];

        u64 acc[4][4];
#pragma unroll
        for (int ch = 0; ch < 4; ch++)
#pragma unroll
            for (int q = 0; q < 4; q++) acc[ch][q] = 0ull;

#pragma unroll
        for (int dz = 0; dz < 3; dz++) {
#pragma unroll
            for (int dy = 0; dy < 3; dy++) {
                long rbase = ((long)zd[dz] * 48 + zh[dy]) * 48;
                float tv[4][3];
#pragma unroll
                for (int ch = 0; ch < 4; ch++) {
                    const float* xc = x + (long)(cq + 8 * ch) * VOX + rbase;
#pragma unroll
                    for (int dx = 0; dx < 3; dx++) tv[ch][dx] = xc[zw[dx]];
                }
#pragma unroll
                for (int dx = 0; dx < 3; dx++) {
                    int n = (dz * 3 + dy) * 3 + dx;
                    const ulonglong2* mp2 = (const ulonglong2*)(mB + n * 8);
                    ulonglong2 mLo = mp2[0];
                    ulonglong2 mHi = mp2[1];
#pragma unroll
                    for (int ch = 0; ch < 4; ch++) {
                        u64 T = dup2(tv[ch][dx]);
                        fma2(acc[ch][0], mLo.x, T);
                        fma2(acc[ch][1], mLo.y, T);
                        fma2(acc[ch][2], mHi.x, T);
                        fma2(acc[ch][3], mHi.y, T);
                    }
                }
            }
        }

#pragma unroll
        for (int ch = 0; ch < 4; ch++) {
            int c = cq + 8 * ch;
#pragma unroll
            for (int i = 0; i < 2; i++)
#pragma unroll
                for (int j = 0; j < 2; j++) {
                    int q = i * 2 + j;
                    long ob = (((long)c * 96 + 2 * d + i) * 96 + 2 * hB + j) * 96 + 2 * v;
                    *(float2*)&out[ob] = *(float2*)&acc[ch][q];
                }
        }
    }
}

// ---------------------------------------------------------------------------
extern "C" void kernel_launch(void* const* d_in, const int* in_sizes, int n_in,
                              void* d_out, int out_size)
{
    const float* x    = (const float*)d_in[0];
    const float* feat = (const float*)d_in[1];
    const float* w1   = (const float*)d_in[2];
    const float* b1   = (const float*)d_in[3];
    const float* w2   = (const float*)d_in[4];
    const float* b2   = (const float*)d_in[5];
    float* out = (float*)d_out;

    const int smemF = 112896;
    cudaFuncSetAttribute(k_fused, cudaFuncAttributeMaxDynamicSharedMemorySize, smemF);

    k_prep<<<271, 256>>>(w1, w2);
    k_prep_feat<<<7200, 256>>>(feat);
    k_fused<<<dim3(24, 48), 256, smemF>>>(b1, x, b2, out);
}

// round 17
// speedup vs baseline: 1.0574x; 1.0574x over previous
#include <cuda_runtime.h>
#include <cuda_bf16.h>
#include <cstdint>

#define VOX (48*48*48)
typedef unsigned long long u64;
typedef unsigned int u32;

// Device globals
__device__ uint4 g_w1f[13824];      // conv1 A frags: [tap27][kc2][mt4][pass2][lane32] uint4 (221 KB)
__device__ u32 g_w2frag[13824];     // conv2 B frags (k-permuted)
__device__ char g_feats[48 * 48 * 50 * 144];  // pre-split features, sF row format

__device__ __forceinline__ void fma2(u64& acc, u64 a, u64 b) {
    asm("fma.rn.f32x2 %0, %1, %2, %0;" : "+l"(acc) : "l"(a), "l"(b));
}
__device__ __forceinline__ u64 dup2(float v) {
    u64 r; asm("mov.b64 %0, {%1, %1};" : "=l"(r) : "f"(v)); return r;
}
__device__ __forceinline__ u32 cvt2bf(float a, float b) {
    u32 r; asm("cvt.rn.bf16x2.f32 %0, %1, %2;" : "=r"(r) : "f"(b), "f"(a)); return r;
}
__device__ __forceinline__ void ldsm4(u32& r0, u32& r1, u32& r2, u32& r3, u32 a) {
    asm volatile("ldmatrix.sync.aligned.m8n8.x4.shared.b16 {%0,%1,%2,%3}, [%4];"
                 : "=r"(r0), "=r"(r1), "=r"(r2), "=r"(r3) : "r"(a));
}
__device__ __forceinline__ void mmabf(float* d, const u32* a, const u32* b) {
    asm volatile(
        "mma.sync.aligned.m16n8k16.row.col.f32.bf16.bf16.f32 "
        "{%0,%1,%2,%3}, {%4,%5,%6,%7}, {%8,%9}, {%0,%1,%2,%3};"
        : "+f"(d[0]), "+f"(d[1]), "+f"(d[2]), "+f"(d[3])
        : "r"(a[0]), "r"(a[1]), "r"(a[2]), "r"(a[3]), "r"(b[0]), "r"(b[1]));
}
__device__ __forceinline__ void cpasync16(u32 dst, const void* src) {
    asm volatile("cp.async.cg.shared.global [%0], [%1], 16;"
                 :: "r"(dst), "l"(src));
}

// ---------------------------------------------------------------------------
// Prep A: w2 B fragments (k-permuted, unchanged) + w1 A fragments.
// ---------------------------------------------------------------------------
extern "C" __global__ void k_prep(const float* __restrict__ w1,
                                  const float* __restrict__ w2)
{
    int id = blockIdx.x * 256 + threadIdx.x;
    if (id < 13824) {
        int breg  = id & 1;
        int entry = id >> 1;
        int lane  = entry & 31;
        int q     = entry >> 5;
        int pass  = q & 1;
        int kt    = (q >> 1) & 3;
        int nt    = q >> 3;
        int tr = lane >> 2, tc = lane & 3;
        int mc = nt * 8 + tr;
        int k0 = kt * 16 + 2 * tc + breg * 8;
        int ocA = ((k0 >> 4) << 4) + ((k0 >> 1) & 7) + ((k0 & 1) << 3);
        int k1 = k0 + 1;
        int ocB = ((k1 >> 4) << 4) + ((k1 >> 1) & 7) + ((k1 & 1) << 3);
        float v0 = w2[mc * 64 + ocA];
        float v1 = w2[mc * 64 + ocB];
        __nv_bfloat16 h0 = __float2bfloat16(v0);
        __nv_bfloat16 h1 = __float2bfloat16(v1);
        u32 out;
        if (pass == 0) {
            out = ((u32)__bfloat16_as_ushort(h1) << 16) | (u32)__bfloat16_as_ushort(h0);
        } else {
            __nv_bfloat16 l0 = __float2bfloat16(v0 - __bfloat162float(h0));
            __nv_bfloat16 l1 = __float2bfloat16(v1 - __bfloat162float(h1));
            out = ((u32)__bfloat16_as_ushort(l1) << 16) | (u32)__bfloat16_as_ushort(l0);
        }
        g_w2frag[id] = out;
    } else if (id < 13824 + 55296) {
        int q = id - 13824;
        int comp = q & 3;
        int lane = (q >> 2) & 31;
        int pass = (q >> 7) & 1;
        int mt   = (q >> 8) & 3;
        int kc   = (q >> 10) & 1;
        int tap  = q >> 11;            // 0..26
        int tr = lane >> 2, tc = lane & 3;
        int oc = mt * 16 + tr + (comp & 1) * 8;
        int k  = kc * 16 + 2 * tc + (comp >> 1) * 8;
        float v0 = w1[oc * 864 + k * 27 + tap];
        float v1 = w1[oc * 864 + (k + 1) * 27 + tap];
        __nv_bfloat16 h0 = __float2bfloat16(v0);
        __nv_bfloat16 h1 = __float2bfloat16(v1);
        u32 out;
        if (pass == 0) {
            out = ((u32)__bfloat16_as_ushort(h1) << 16) | (u32)__bfloat16_as_ushort(h0);
        } else {
            __nv_bfloat16 l0 = __float2bfloat16(v0 - __bfloat162float(h0));
            __nv_bfloat16 l1 = __float2bfloat16(v1 - __bfloat162float(h1));
            out = ((u32)__bfloat16_as_ushort(l1) << 16) | (u32)__bfloat16_as_ushort(l0);
        }
        ((u32*)g_w1f)[q] = out;
    }
}

// ---------------------------------------------------------------------------
// Prep B: features -> bf16 hi/lo rows (unchanged)
// ---------------------------------------------------------------------------
extern "C" __global__ void k_prep_feat(const float* __restrict__ feat)
{
    int id = blockIdx.x * 256 + threadIdx.x;
    if (id >= 48 * 48 * 50 * 16) return;
    int ci2 = id & 15;
    int q   = id >> 4;
    int wp  = q % 50;
    int row = q;
    int y   = (q / 50) % 48;
    int z   = q / (50 * 48);
    int w = min(max(wp - 1, 0), 47);
    long gi = (long)(2 * ci2) * VOX + (z * 48 + y) * 48 + w;
    float f0 = feat[gi];
    float f1 = feat[gi + VOX];
    u32 hp = cvt2bf(f0, f1);
    float r0 = f0 - __uint_as_float(hp << 16);
    float r1 = f1 - __uint_as_float(hp & 0xffff0000u);
    u32 lp = cvt2bf(r0, r1);
    char* dst = g_feats + (size_t)row * 144;
    *(u32*)(dst + ci2 * 4)      = hp;
    *(u32*)(dst + 64 + ci2 * 4) = lp;
}

// ---------------------------------------------------------------------------
// Fused kernel, 256 threads, 2 CTAs/SM, grid (24,48). Block = (d, 2 h-rows).
// conv1: A direct from g_w1f (LDG.128), B from sF ldsm; F-only 3-stage pipe.
// Warps: mw = warp&1, nw = (warp>>1)&1, kcw = warp>>2. Tile 2m x 6n x 1kc.
// smem (110592 B): sF 2x28800 [0,57600) ; exchange [57600,82176) ;
//                  phase2 sHu [0,26112) ; phase3 sMt [26112,110592)
// ---------------------------------------------------------------------------
extern "C" __global__ void __launch_bounds__(256, 2) k_fused(
    const float* __restrict__ b1, const float* __restrict__ x,
    const float* __restrict__ b2, float* __restrict__ out)
{
    extern __shared__ char sm[];
    const u32 sFb = (u32)__cvta_generic_to_shared(sm);

    const int tid  = threadIdx.x;
    const int lane = tid & 31;
    const int warp = tid >> 5;
    const int mw  = warp & 1;
    const int nw  = (warp >> 1) & 1;
    const int kcw = warp >> 2;
    const int grp = lane >> 3, r8 = lane & 7;
    const int tr = lane >> 2, tc = lane & 3;
    const int h0 = blockIdx.x * 2;
    const int d  = blockIdx.y;

    auto issueF = [&](int dz, int buf) {
        int z = min(max(d - 1 + dz, 0), 47);
        u32 dst = sFb + buf * 28800;
#pragma unroll
        for (int hh = 0; hh < 4; hh++) {
            int y = min(max(h0 - 1 + hh, 0), 47);
            const char* src = g_feats + (size_t)((z * 48 + y) * 50) * 144;
            for (int t = tid; t < 450; t += 256)
                cpasync16(dst + hh * 7200 + t * 16, src + t * 16);
        }
    };

    // ======================= Phase 1: conv1 (F-only 3-stage pipe) ===========
    float D[2][6][4];
#pragma unroll
    for (int i = 0; i < 2; i++)
#pragma unroll
        for (int j = 0; j < 6; j++)
#pragma unroll
            for (int c = 0; c < 4; c++) D[i][j][c] = 0.0f;

    issueF(0, 0);
    asm volatile("cp.async.commit_group;" ::: "memory");

    const uint4* w1f = g_w1f;

#pragma unroll 1
    for (int dz = 0; dz < 3; dz++) {
        const int fbuf = dz & 1;
        asm volatile("cp.async.wait_group 0;" ::: "memory");
        __syncthreads();
        if (dz < 2) {
            issueF(dz + 1, fbuf ^ 1);
            asm volatile("cp.async.commit_group;" ::: "memory");
        }

        const u32 fBase = sFb + fbuf * 28800;
#pragma unroll 1
        for (int dy = 0; dy < 3; dy++) {
#pragma unroll 1
            for (int dx = 0; dx < 3; dx++) {
                const int tap = dz * 9 + dy * 3 + dx;
                const int rowBase = (nw + dy) * 50 + dx;
                // A fragments: 4x LDG.128, coalesced, L1/L2-hot
                const uint4* fr = w1f + (size_t)(tap * 2 + kcw) * 256
                                + (size_t)(2 * mw) * 64 + lane;
                uint4 Ah0 = fr[0];
                uint4 Al0 = fr[32];
                uint4 Ah1 = fr[64];
                uint4 Al1 = fr[96];
                // B: 6 n8 tiles, hi and lo (3 x4 each), kc = kcw
                u32 bh[6][2], bl[6][2];
#pragma unroll
                for (int jj = 0; jj < 3; jj++) {
                    int rowI = rowBase + jj * 16 + (grp >> 1) * 8 + r8;
                    u32 bb = fBase + rowI * 144 + (grp & 1) * 16 + kcw * 32;
                    ldsm4(bh[2 * jj][0], bh[2 * jj][1],
                          bh[2 * jj + 1][0], bh[2 * jj + 1][1], bb);
                    ldsm4(bl[2 * jj][0], bl[2 * jj][1],
                          bl[2 * jj + 1][0], bl[2 * jj + 1][1], bb + 64);
                }
#pragma unroll
                for (int j = 0; j < 6; j++) {
                    mmabf(D[0][j], (const u32*)&Ah0, bh[j]);
                    mmabf(D[0][j], (const u32*)&Al0, bh[j]);
                    mmabf(D[0][j], (const u32*)&Ah0, bl[j]);
                    mmabf(D[1][j], (const u32*)&Ah1, bh[j]);
                    mmabf(D[1][j], (const u32*)&Al1, bh[j]);
                    mmabf(D[1][j], (const u32*)&Ah1, bl[j]);
                }
            }
        }
    }
    __syncthreads();   // all warps done reading sF

    // ====== kc-partial exchange ======
    float* ex = (float*)(sm + 57600);   // 24576 B
    const int pair = nw * 2 + mw;
    if (kcw == 1) {
#pragma unroll
        for (int i = 0; i < 2; i++)
#pragma unroll
            for (int j = 0; j < 6; j++)
                *(float4*)&ex[(((pair * 12) + i * 6 + j) * 32 + lane) * 4] =
                    *(float4*)D[i][j];
    }
    __syncthreads();

    // ====== Phase 2: reduce + silu + bf16 hi/lo split into sHu ==============
    u32* sHu = (u32*)sm;
    const u32 sHb = sFb;
    if (kcw == 0) {
#pragma unroll
        for (int i = 0; i < 2; i++) {
            int oc0 = (2 * mw + i) * 16 + tr;
            int jcol = (2 * mw + i) * 8 + tr;
            float bias0 = b1[oc0], bias1 = b1[oc0 + 8];
#pragma unroll
            for (int j = 0; j < 6; j++) {
                float4 o = *(float4*)&ex[(((pair * 12) + i * 6 + j) * 32 + lane) * 4];
                int vl = nw * 48 + j * 8 + 2 * tc;
                float v0 = D[i][j][0] + o.x + bias0;
                float v1 = D[i][j][1] + o.y + bias0;
                float v2 = D[i][j][2] + o.z + bias1;
                float v3 = D[i][j][3] + o.w + bias1;
                v0 = v0 / (1.0f + __expf(-v0));
                v1 = v1 / (1.0f + __expf(-v1));
                v2 = v2 / (1.0f + __expf(-v2));
                v3 = v3 / (1.0f + __expf(-v3));
                u32 hp0 = cvt2bf(v0, v2);
                u32 hp1 = cvt2bf(v1, v3);
                u32 lp0 = cvt2bf(v0 - __uint_as_float(hp0 << 16),
                                 v2 - __uint_as_float(hp0 & 0xffff0000u));
                u32 lp1 = cvt2bf(v1 - __uint_as_float(hp1 << 16),
                                 v3 - __uint_as_float(hp1 & 0xffff0000u));
                sHu[vl * 68 + jcol]            = hp0;
                sHu[vl * 68 + 32 + jcol]       = lp0;
                sHu[(vl + 1) * 68 + jcol]      = hp1;
                sHu[(vl + 1) * 68 + 32 + jcol] = lp1;
            }
        }
    }
    __syncthreads();

    // ======================= Phase 3: conv2 GEMM -> softmax -> apply =======
    float* sMt = (float*)(sm + 26112);   // 96 x 220 fp32
    const uint2* w2f = (const uint2*)g_w2frag;

    {
        const int nnt = (warp < 3) ? 4 : 3;
#pragma unroll 1
        for (int mh = 0; mh < 2; mh++) {
            float Dv[4][3][4];
#pragma unroll
            for (int t = 0; t < 4; t++)
#pragma unroll
                for (int mi = 0; mi < 3; mi++)
#pragma unroll
                    for (int c = 0; c < 4; c++) Dv[t][mi][c] = 0.0f;

#pragma unroll
            for (int kt = 0; kt < 4; kt++) {
                u32 ah[3][4], al[3][4];
#pragma unroll
                for (int mi = 0; mi < 3; mi++) {
                    int mt = mh * 3 + mi;
                    u32 ab = sHb + (mt * 16 + (grp & 1) * 8 + r8) * 272
                           + (grp >> 1) * 16 + kt * 32;
                    ldsm4(ah[mi][0], ah[mi][1], ah[mi][2], ah[mi][3], ab);
                    ldsm4(al[mi][0], al[mi][1], al[mi][2], al[mi][3], ab + 128);
                }
#pragma unroll
                for (int t = 0; t < 4; t++) {
                    if (t >= nnt) break;
                    int nt = warp + 8 * t;
                    uint2 bhv = w2f[((nt * 4 + kt) * 2 + 0) * 32 + lane];
                    uint2 blv = w2f[((nt * 4 + kt) * 2 + 1) * 32 + lane];
                    u32 bh2[2] = { bhv.x, bhv.y };
                    u32 bl2[2] = { blv.x, blv.y };
#pragma unroll
                    for (int mi = 0; mi < 3; mi++) {
                        mmabf(Dv[t][mi], ah[mi], bh2);
                        mmabf(Dv[t][mi], al[mi], bh2);
                        mmabf(Dv[t][mi], ah[mi], bl2);
                    }
                }
            }
#pragma unroll
            for (int t = 0; t < 4; t++) {
                if (t >= nnt) break;
                int nt = warp + 8 * t;
                int mcA = nt * 8 + 2 * tc;
                int mcB = mcA + 1;
                float bA = b2[mcA], bB = b2[mcB];
                int iA = (mcA % 27) * 8 + mcA / 27;
                int iB = (mcB % 27) * 8 + mcB / 27;
#pragma unroll
                for (int mi = 0; mi < 3; mi++) {
                    int v0 = (mh * 3 + mi) * 16 + tr;
                    sMt[v0 * 220 + iA]       = Dv[t][mi][0] + bA;
                    sMt[v0 * 220 + iB]       = Dv[t][mi][1] + bB;
                    sMt[(v0 + 8) * 220 + iA] = Dv[t][mi][2] + bA;
                    sMt[(v0 + 8) * 220 + iB] = Dv[t][mi][3] + bB;
                }
            }
        }
    }
    __syncthreads();

    // --- softmax over n per (vl, g-pair) ---
    for (int s = tid; s < 384; s += 256) {
        int vl = s >> 2, gp = s & 3;
        float* p = &sMt[vl * 220 + 2 * gp];
        float2 m0 = *(float2*)p;
        float mx0 = m0.x, mx1 = m0.y;
#pragma unroll
        for (int n = 1; n < 27; n++) {
            float2 mv = *(float2*)(p + n * 8);
            mx0 = fmaxf(mx0, mv.x);
            mx1 = fmaxf(mx1, mv.y);
        }
        float e0[27], e1[27];
        float s0 = 0.0f, s1 = 0.0f;
#pragma unroll
        for (int n = 0; n < 27; n++) {
            float2 mv = *(float2*)(p + n * 8);
            e0[n] = __expf(mv.x - mx0); s0 += e0[n];
            e1[n] = __expf(mv.y - mx1); s1 += e1[n];
        }
        float i0 = 1.0f / s0, i1 = 1.0f / s1;
#pragma unroll
        for (int n = 0; n < 27; n++)
            *(float2*)(p + n * 8) = make_float2(e0[n] * i0, e1[n] * i1);
    }
    __syncthreads();

    // --- apply ---
    int zd[3];
#pragma unroll
    for (int t = 0; t < 3; t++) zd[t] = min(max(d + t - 1, 0), 47);

#pragma unroll 1
    for (int p = tid; p < 768; p += 256) {
        int vl = p % 96, cq = p / 96;
        int hr = (vl >= 48);
        int v  = vl - (hr ? 48 : 0);
        int hB = h0 + hr;
        int zh[3], zw[3];
#pragma unroll
        for (int t = 0; t < 3; t++) zh[t] = min(max(hB + t - 1, 0), 47);
        zw[0] = max(v - 1, 0); zw[1] = v; zw[2] = min(v + 1, 47);
        const float* mB = &sMt[vl * 220];

        u64 acc[4][4];
#pragma unroll
        for (int ch = 0; ch < 4; ch++)
#pragma unroll
            for (int q = 0; q < 4; q++) acc[ch][q] = 0ull;

#pragma unroll
        for (int dz = 0; dz < 3; dz++) {
#pragma unroll
            for (int dy = 0; dy < 3; dy++) {
                long rbase = ((long)zd[dz] * 48 + zh[dy]) * 48;
                float tv[4][3];
#pragma unroll
                for (int ch = 0; ch < 4; ch++) {
                    const float* xc = x + (long)(cq + 8 * ch) * VOX + rbase;
#pragma unroll
                    for (int dx = 0; dx < 3; dx++) tv[ch][dx] = xc[zw[dx]];
                }
#pragma unroll
                for (int dx = 0; dx < 3; dx++) {
                    int n = (dz * 3 + dy) * 3 + dx;
                    const ulonglong2* mp2 = (const ulonglong2*)(mB + n * 8);
                    ulonglong2 mLo = mp2[0];
                    ulonglong2 mHi = mp2[1];
#pragma unroll
                    for (int ch = 0; ch < 4; ch++) {
                        u64 T = dup2(tv[ch][dx]);
                        fma2(acc[ch][0], mLo.x, T);
                        fma2(acc[ch][1], mLo.y, T);
                        fma2(acc[ch][2], mHi.x, T);
                        fma2(acc[ch][3], mHi.y, T);
                    }
                }
            }
        }

#pragma unroll
        for (int ch = 0; ch < 4; ch++) {
            int c = cq + 8 * ch;
#pragma unroll
            for (int i = 0; i < 2; i++)
#pragma unroll
                for (int j = 0; j < 2; j++) {
                    int q = i * 2 + j;
                    long ob = (((long)c * 96 + 2 * d + i) * 96 + 2 * hB + j) * 96 + 2 * v;
                    *(float2*)&out[ob] = *(float2*)&acc[ch][q];
                }
        }
    }
}

// ---------------------------------------------------------------------------
extern "C" void kernel_launch(void* const* d_in, const int* in_sizes, int n_in,
                              void* d_out, int out_size)
{
    const float* x    = (const float*)d_in[0];
    const float* feat = (const float*)d_in[1];
    const float* w1   = (const float*)d_in[2];
    const float* b1   = (const float*)d_in[3];
    const float* w2   = (const float*)d_in[4];
    const float* b2   = (const float*)d_in[5];
    float* out = (float*)d_out;

    const int smemF = 110592;
    cudaFuncSetAttribute(k_fused, cudaFuncAttributeMaxDynamicSharedMemorySize, smemF);

    k_prep<<<270, 256>>>(w1, w2);
    k_prep_feat<<<7200, 256>>>(feat);
    k_fused<<<dim3(24, 48), 256, smemF>>>(b1, x, b2, out);
}